// round 1
// baseline (speedup 1.0000x reference)
#include <cuda_runtime.h>
#include <cuda_bf16.h>
#include <math.h>

// Problem constants
#define BATCH 4
#define SEQ 4096
#define DIM 1024
#define NHEAD 16
#define HDIM 64
#define M_ROWS (BATCH * SEQ)      // 16384
#define QKV_COLS (3 * DIM)        // 3072

// Scratch (device globals; allocation-free contract)
__device__ float g_qkv[(size_t)M_ROWS * QKV_COLS];   // ~201 MB
__device__ float g_attn[(size_t)M_ROWS * DIM];       // ~67 MB
__device__ float g_kv[BATCH * NHEAD * HDIM * HDIM];  // 1 MB
__device__ float g_ksum[BATCH * NHEAD * HDIM];

// ---------------------------------------------------------------------------
// SGEMM: C[M,N] = A[M,K] @ B[K,N], row-major. 128x128 tile, kTile=8,
// 256 threads, 8x8 per-thread register tile.
// MODE 0: plain store
// MODE 1: elu(x)+1 applied to columns < 2048 (q and k parts of qkv)
// MODE 2: += bias[col]
// ---------------------------------------------------------------------------
template <int MODE>
__global__ __launch_bounds__(256) void sgemm_kernel(
    const float* __restrict__ A, const float* __restrict__ B,
    float* __restrict__ C, int M, int N, int K,
    const float* __restrict__ bias)
{
    __shared__ float As[8][128];
    __shared__ float Bs[8][128];

    const int tid = threadIdx.x;
    const int bm = blockIdx.y * 128;
    const int bn = blockIdx.x * 128;

    // A tile loader: 128 rows x 8 cols; each thread one float4
    const int a_row = tid >> 1;
    const int a_col = (tid & 1) * 4;
    // B tile loader: 8 rows x 128 cols; each thread one float4
    const int b_row = tid >> 5;
    const int b_col = (tid & 31) * 4;

    const int tx = tid & 15;
    const int ty = tid >> 4;
    const int m0 = ty * 4;        // rows m0..m0+3 and m0+64..m0+67
    const int n0 = tx * 4;        // cols n0..n0+3 and n0+64..n0+67

    float acc[8][8];
#pragma unroll
    for (int i = 0; i < 8; i++)
#pragma unroll
        for (int j = 0; j < 8; j++) acc[i][j] = 0.f;

    const float* Aptr = A + (size_t)(bm + a_row) * K + a_col;
    const float* Bptr = B + (size_t)b_row * N + bn + b_col;

    for (int k0 = 0; k0 < K; k0 += 8) {
        float4 av = *reinterpret_cast<const float4*>(Aptr + k0);
        float4 bv = *reinterpret_cast<const float4*>(Bptr + (size_t)k0 * N);
        As[a_col + 0][a_row] = av.x;
        As[a_col + 1][a_row] = av.y;
        As[a_col + 2][a_row] = av.z;
        As[a_col + 3][a_row] = av.w;
        *reinterpret_cast<float4*>(&Bs[b_row][b_col]) = bv;
        __syncthreads();

#pragma unroll
        for (int kk = 0; kk < 8; kk++) {
            float ra[8], rb[8];
            *reinterpret_cast<float4*>(&ra[0]) = *reinterpret_cast<float4*>(&As[kk][m0]);
            *reinterpret_cast<float4*>(&ra[4]) = *reinterpret_cast<float4*>(&As[kk][m0 + 64]);
            *reinterpret_cast<float4*>(&rb[0]) = *reinterpret_cast<float4*>(&Bs[kk][n0]);
            *reinterpret_cast<float4*>(&rb[4]) = *reinterpret_cast<float4*>(&Bs[kk][n0 + 64]);
#pragma unroll
            for (int i = 0; i < 8; i++)
#pragma unroll
                for (int j = 0; j < 8; j++)
                    acc[i][j] = fmaf(ra[i], rb[j], acc[i][j]);
        }
        __syncthreads();
    }

    const bool do_elu = (MODE == 1) && (bn < 2048);  // q/k columns only

#pragma unroll
    for (int i = 0; i < 8; i++) {
        int gm = bm + ((i < 4) ? (m0 + i) : (m0 + 64 + i - 4));
#pragma unroll
        for (int half = 0; half < 2; half++) {
            int gn = bn + ((half == 0) ? n0 : (n0 + 64));
            float v0 = acc[i][half * 4 + 0];
            float v1 = acc[i][half * 4 + 1];
            float v2 = acc[i][half * 4 + 2];
            float v3 = acc[i][half * 4 + 3];
            if (MODE == 1 && do_elu) {
                v0 = (v0 > 0.f) ? (v0 + 1.f) : __expf(0.f) * expf(v0); // expf(v0)
                v0 = (acc[i][half * 4 + 0] > 0.f) ? (acc[i][half * 4 + 0] + 1.f) : expf(acc[i][half * 4 + 0]);
                v1 = (v1 > 0.f) ? (v1 + 1.f) : expf(acc[i][half * 4 + 1]);
                v2 = (v2 > 0.f) ? (v2 + 1.f) : expf(acc[i][half * 4 + 2]);
                v3 = (v3 > 0.f) ? (v3 + 1.f) : expf(acc[i][half * 4 + 3]);
            }
            if (MODE == 2) {
                v0 += bias[gn + 0];
                v1 += bias[gn + 1];
                v2 += bias[gn + 2];
                v3 += bias[gn + 3];
            }
            float4 out = make_float4(v0, v1, v2, v3);
            *reinterpret_cast<float4*>(&C[(size_t)gm * N + gn]) = out;
        }
    }
}

// ---------------------------------------------------------------------------
// K2: per (b,h): kv[d][e] = sum_n k[n,d]*v[n,e];  ksum[d] = sum_n k[n,d]
// One block per (b,h). 256 threads, each computes a 4x4 tile of the 64x64 kv.
// ---------------------------------------------------------------------------
__global__ __launch_bounds__(256) void kv_state_kernel()
{
    const int bh = blockIdx.x;              // 0..63
    const int b = bh >> 4, h = bh & 15;

    __shared__ float Ks[32][64];
    __shared__ float Vs[32][64];

    const int tid = threadIdx.x;
    const int tx = tid & 15, ty = tid >> 4;

    // tile loader: 32 rows x 64 cols => 8 floats per thread (2x float4)
    const int lr = tid >> 3;
    const int lc = (tid & 7) * 8;

    const float* base = g_qkv + (size_t)b * SEQ * QKV_COLS;
    const int k_col = DIM + h * HDIM;       // 1024 + h*64
    const int v_col = 2 * DIM + h * HDIM;   // 2048 + h*64

    float acc[4][4];
#pragma unroll
    for (int i = 0; i < 4; i++)
#pragma unroll
        for (int j = 0; j < 4; j++) acc[i][j] = 0.f;
    float ksum = 0.f;

    for (int n0 = 0; n0 < SEQ; n0 += 32) {
        const float* kp = base + (size_t)(n0 + lr) * QKV_COLS + k_col + lc;
        const float* vp = base + (size_t)(n0 + lr) * QKV_COLS + v_col + lc;
        *reinterpret_cast<float4*>(&Ks[lr][lc])     = *reinterpret_cast<const float4*>(kp);
        *reinterpret_cast<float4*>(&Ks[lr][lc + 4]) = *reinterpret_cast<const float4*>(kp + 4);
        *reinterpret_cast<float4*>(&Vs[lr][lc])     = *reinterpret_cast<const float4*>(vp);
        *reinterpret_cast<float4*>(&Vs[lr][lc + 4]) = *reinterpret_cast<const float4*>(vp + 4);
        __syncthreads();

#pragma unroll 8
        for (int kk = 0; kk < 32; kk++) {
            float rk[4], rv[4];
            *reinterpret_cast<float4*>(rk) = *reinterpret_cast<float4*>(&Ks[kk][ty * 4]);
            *reinterpret_cast<float4*>(rv) = *reinterpret_cast<float4*>(&Vs[kk][tx * 4]);
#pragma unroll
            for (int i = 0; i < 4; i++)
#pragma unroll
                for (int j = 0; j < 4; j++)
                    acc[i][j] = fmaf(rk[i], rv[j], acc[i][j]);
        }
        if (tid < 64) {
#pragma unroll
            for (int kk = 0; kk < 32; kk++) ksum += Ks[kk][tid];
        }
        __syncthreads();
    }

    float* kvout = g_kv + (size_t)bh * HDIM * HDIM;
#pragma unroll
    for (int i = 0; i < 4; i++) {
        float4 v = make_float4(acc[i][0], acc[i][1], acc[i][2], acc[i][3]);
        *reinterpret_cast<float4*>(&kvout[(ty * 4 + i) * HDIM + tx * 4]) = v;
    }
    if (tid < 64) g_ksum[bh * HDIM + tid] = ksum;
}

// ---------------------------------------------------------------------------
// K3: out[b,n,h*64+e] = z * sum_d q[b,n,h,d] * kv[bh][d][e]
//     z = 1 / (sum_d q[b,n,h,d]*ksum[bh][d] + 1e-6)
// grid: (SEQ/64, B*H). Block 256 threads, 64 rows x 64 cols output tile.
// ---------------------------------------------------------------------------
__global__ __launch_bounds__(256) void attn_out_kernel()
{
    const int bh = blockIdx.y;
    const int b = bh >> 4, h = bh & 15;
    const int n0 = blockIdx.x * 64;

    __shared__ float Qs[64][65];   // padded: conflict-free z dot-products
    __shared__ float KVs[64 * 64];
    __shared__ float ksums[64];
    __shared__ float zsh[64];

    const int tid = threadIdx.x;

    // Load kv state (flat float4 copy)
    const float* kvsrc = g_kv + (size_t)bh * HDIM * HDIM;
    for (int i = tid; i < (HDIM * HDIM) / 4; i += 256)
        reinterpret_cast<float4*>(KVs)[i] = reinterpret_cast<const float4*>(kvsrc)[i];
    if (tid < 64) ksums[tid] = g_ksum[bh * HDIM + tid];

    // Load Q tile [64 rows][64 dims]
    {
        const int qr = tid >> 2;             // 0..63
        const int qc = (tid & 3) * 16;       // 0,16,32,48
        const float* qbase = g_qkv + (size_t)(b * SEQ + n0 + qr) * QKV_COLS + h * HDIM + qc;
#pragma unroll
        for (int c = 0; c < 16; c += 4) {
            float4 v = *reinterpret_cast<const float4*>(qbase + c);
            Qs[qr][qc + c + 0] = v.x;
            Qs[qr][qc + c + 1] = v.y;
            Qs[qr][qc + c + 2] = v.z;
            Qs[qr][qc + c + 3] = v.w;
        }
    }
    __syncthreads();

    // z per row
    if (tid < 64) {
        float dot = 0.f;
#pragma unroll 8
        for (int d = 0; d < 64; d++) dot = fmaf(Qs[tid][d], ksums[d], dot);
        zsh[tid] = 1.f / (dot + 1e-6f);
    }
    __syncthreads();

    const int tx = tid & 15, ty = tid >> 4;
    const int r0 = ty * 4;
    const int e0 = tx * 4;

    float acc[4][4];
#pragma unroll
    for (int i = 0; i < 4; i++)
#pragma unroll
        for (int j = 0; j < 4; j++) acc[i][j] = 0.f;

#pragma unroll 4
    for (int d = 0; d < 64; d++) {
        float rb[4];
        *reinterpret_cast<float4*>(rb) = *reinterpret_cast<float4*>(&KVs[d * 64 + e0]);
        float ra0 = Qs[r0 + 0][d];
        float ra1 = Qs[r0 + 1][d];
        float ra2 = Qs[r0 + 2][d];
        float ra3 = Qs[r0 + 3][d];
#pragma unroll
        for (int j = 0; j < 4; j++) {
            acc[0][j] = fmaf(ra0, rb[j], acc[0][j]);
            acc[1][j] = fmaf(ra1, rb[j], acc[1][j]);
            acc[2][j] = fmaf(ra2, rb[j], acc[2][j]);
            acc[3][j] = fmaf(ra3, rb[j], acc[3][j]);
        }
    }

#pragma unroll
    for (int i = 0; i < 4; i++) {
        float z = zsh[r0 + i];
        float4 v = make_float4(acc[i][0] * z, acc[i][1] * z, acc[i][2] * z, acc[i][3] * z);
        size_t row = (size_t)(b * SEQ + n0 + r0 + i);
        *reinterpret_cast<float4*>(&g_attn[row * DIM + h * HDIM + e0]) = v;
    }
}

// ---------------------------------------------------------------------------
extern "C" void kernel_launch(void* const* d_in, const int* in_sizes, int n_in,
                              void* d_out, int out_size)
{
    const float* x      = (const float*)d_in[0];  // [4,4096,1024]
    const float* W_qkv  = (const float*)d_in[1];  // [1024,3072]
    const float* W_proj = (const float*)d_in[2];  // [1024,1024]
    const float* b_proj = (const float*)d_in[3];  // [1024]
    float* out = (float*)d_out;

    float *qkv_ptr, *attn_ptr;
    cudaGetSymbolAddress((void**)&qkv_ptr, g_qkv);
    cudaGetSymbolAddress((void**)&attn_ptr, g_attn);

    // K1: qkv = x @ W_qkv, with elu+1 fused on q/k columns
    sgemm_kernel<1><<<dim3(QKV_COLS / 128, M_ROWS / 128), 256>>>(
        x, W_qkv, qkv_ptr, M_ROWS, QKV_COLS, DIM, nullptr);

    // K2: kv state + ksum per (b,h)
    kv_state_kernel<<<BATCH * NHEAD, 256>>>();

    // K3: normalized readout -> g_attn [16384, 1024]
    attn_out_kernel<<<dim3(SEQ / 64, BATCH * NHEAD), 256>>>();

    // K4: out = g_attn @ W_proj + b_proj
    sgemm_kernel<2><<<dim3(DIM / 128, M_ROWS / 128), 256>>>(
        attn_ptr, W_proj, out, M_ROWS, DIM, DIM, b_proj);
}

// round 3
// speedup vs baseline: 2.5710x; 2.5710x over previous
#include <cuda_runtime.h>
#include <math.h>
#include <stdint.h>

// ---------------------------------------------------------------------------
// Problem constants
// ---------------------------------------------------------------------------
#define BATCH 4
#define SEQ 4096
#define DIM 1024
#define NHEAD 16
#define HDIM 64
#define M_ROWS (BATCH * SEQ)      // 16384
#define QKV_COLS (3 * DIM)        // 3072

// Scratch (device globals; allocation-free contract)
__device__ float g_qkv[(size_t)M_ROWS * QKV_COLS];
__device__ float g_attn[(size_t)M_ROWS * DIM];
__device__ float g_kv[BATCH * NHEAD * HDIM * HDIM];
__device__ float g_ksum[BATCH * NHEAD * HDIM];

// ---------------------------------------------------------------------------
// Smem geometry for the mma GEMM (pitches picked for conflict-free frag LDS)
// ---------------------------------------------------------------------------
#define APITCH 36                       // floats per A row (128B rows + pad)
#define BPITCH 136                      // floats per B row
#define A_ST_FLOATS (128 * APITCH)      // 4608
#define B_ST_FLOATS (32 * BPITCH)       // 4352
#define SMEM_FLOATS (2 * (A_ST_FLOATS + B_ST_FLOATS))
#define SMEM_BYTES (SMEM_FLOATS * 4)    // 71680

__device__ __forceinline__ uint32_t smem_u32(const void* p) {
    uint32_t a;
    asm("{ .reg .u64 t; cvta.to.shared.u64 t, %1; cvt.u32.u64 %0, t; }"
        : "=r"(a) : "l"(p));
    return a;
}
__device__ __forceinline__ void cp16(uint32_t dst, const void* src) {
    asm volatile("cp.async.cg.shared.global [%0], [%1], 16;" :: "r"(dst), "l"(src));
}
__device__ __forceinline__ uint32_t tf32r(float f) {
    uint32_t u;
    asm("cvt.rna.tf32.f32 %0, %1;" : "=r"(u) : "f"(f));
    return u;
}
__device__ __forceinline__ void mma_m16n8k8(float* c, const uint32_t* a, const uint32_t* b) {
    asm volatile(
        "mma.sync.aligned.m16n8k8.row.col.f32.tf32.tf32.f32 "
        "{%0,%1,%2,%3}, {%4,%5,%6,%7}, {%8,%9}, {%0,%1,%2,%3};"
        : "+f"(c[0]), "+f"(c[1]), "+f"(c[2]), "+f"(c[3])
        : "r"(a[0]), "r"(a[1]), "r"(a[2]), "r"(a[3]), "r"(b[0]), "r"(b[1]));
}

// ---------------------------------------------------------------------------
// Tensor-core GEMM: C[M,N] = A[M,1024] @ B[1024,N]  (both row-major)
// CTA 128x128, 8 warps (warp tile 32x64), K-tile 32, cp.async double buffer.
// MODE 1: elu(v)+1 on global cols < 2048 ; MODE 2: v += bias[col]
// ---------------------------------------------------------------------------
template <int MODE>
__global__ __launch_bounds__(256) void gemm_mma(
    const float* __restrict__ A, const float* __restrict__ B,
    float* __restrict__ C, int N, const float* __restrict__ bias)
{
    extern __shared__ float sm[];
    float* As = sm;                       // [2][128][APITCH]
    float* Bs = sm + 2 * A_ST_FLOATS;     // [2][32][BPITCH]

    const int tid = threadIdx.x;
    const int bm = blockIdx.y * 128;
    const int bn = blockIdx.x * 128;
    const int lane = tid & 31, wid = tid >> 5;
    const int g = lane >> 2, tg = lane & 3;
    const int mw = (wid >> 1) * 32;       // warp M offset in tile
    const int nw = (wid & 1) * 64;        // warp N offset in tile

    float acc[2][8][4];
#pragma unroll
    for (int mi = 0; mi < 2; mi++)
#pragma unroll
        for (int ni = 0; ni < 8; ni++)
#pragma unroll
            for (int j = 0; j < 4; j++) acc[mi][ni][j] = 0.f;

    const uint32_t sA = smem_u32(As);
    const uint32_t sB = smem_u32(Bs);

    // ---- tile loader (cp.async, 16B chunks) ----
    auto load_tile = [&](int kt, int s) {
        // A: 128 rows x 32 floats = 1024 chunks of 4 floats; 4 per thread
#pragma unroll
        for (int i = 0; i < 4; i++) {
            int c = tid + i * 256;
            int row = c >> 3;
            int off = (c & 7) * 4;
            const float* gp = A + (size_t)(bm + row) * DIM + kt * 32 + off;
            cp16(sA + (s * A_ST_FLOATS + row * APITCH + off) * 4, gp);
        }
        // B: 32 rows x 128 floats = 1024 chunks; 4 per thread
#pragma unroll
        for (int i = 0; i < 4; i++) {
            int c = tid + i * 256;
            int row = c >> 5;
            int col = (c & 31) * 4;
            const float* gp = B + (size_t)(kt * 32 + row) * N + bn + col;
            cp16(sB + (s * B_ST_FLOATS + row * BPITCH + col) * 4, gp);
        }
        asm volatile("cp.async.commit_group;" ::: "memory");
    };

    load_tile(0, 0);

    const int NT = DIM / 32;              // 32 k-tiles
    for (int kt = 0; kt < NT; ++kt) {
        const int s = kt & 1;
        if (kt + 1 < NT) {
            load_tile(kt + 1, (kt + 1) & 1);
            asm volatile("cp.async.wait_group 1;" ::: "memory");
        } else {
            asm volatile("cp.async.wait_group 0;" ::: "memory");
        }
        __syncthreads();

        const float* pa = As + s * A_ST_FLOATS;
        const float* pb = Bs + s * B_ST_FLOATS;

#pragma unroll
        for (int ks = 0; ks < 4; ks++) {
            const int k0 = ks * 8;
            uint32_t af[2][4];
#pragma unroll
            for (int mi = 0; mi < 2; mi++) {
                const int r0 = mw + mi * 16;
                af[mi][0] = tf32r(pa[(r0 + g) * APITCH + k0 + tg]);
                af[mi][1] = tf32r(pa[(r0 + g + 8) * APITCH + k0 + tg]);
                af[mi][2] = tf32r(pa[(r0 + g) * APITCH + k0 + tg + 4]);
                af[mi][3] = tf32r(pa[(r0 + g + 8) * APITCH + k0 + tg + 4]);
            }
            uint32_t bf[8][2];
#pragma unroll
            for (int ni = 0; ni < 8; ni++) {
                bf[ni][0] = tf32r(pb[(k0 + tg) * BPITCH + nw + ni * 8 + g]);
                bf[ni][1] = tf32r(pb[(k0 + tg + 4) * BPITCH + nw + ni * 8 + g]);
            }
#pragma unroll
            for (int mi = 0; mi < 2; mi++)
#pragma unroll
                for (int ni = 0; ni < 8; ni++)
                    mma_m16n8k8(acc[mi][ni], af[mi], bf[ni]);
        }
        __syncthreads();                  // stage s free for tile kt+2
    }

    // ---- epilogue: direct global stores (32B sectors) ----
#pragma unroll
    for (int mi = 0; mi < 2; mi++) {
#pragma unroll
        for (int ni = 0; ni < 8; ni++) {
            const int row0 = bm + mw + mi * 16 + g;
            const int col = bn + nw + ni * 8 + 2 * tg;
            float v0 = acc[mi][ni][0], v1 = acc[mi][ni][1];
            float v2 = acc[mi][ni][2], v3 = acc[mi][ni][3];
            if (MODE == 1 && col < 2048) {          // elu(x)+1 on q,k columns
                v0 = (v0 > 0.f) ? (v0 + 1.f) : expf(v0);
                v1 = (v1 > 0.f) ? (v1 + 1.f) : expf(v1);
                v2 = (v2 > 0.f) ? (v2 + 1.f) : expf(v2);
                v3 = (v3 > 0.f) ? (v3 + 1.f) : expf(v3);
            }
            if (MODE == 2) {
                float b0 = __ldg(&bias[col]), b1 = __ldg(&bias[col + 1]);
                v0 += b0; v1 += b1; v2 += b0; v3 += b1;
            }
            *reinterpret_cast<float2*>(&C[(size_t)row0 * N + col]) = make_float2(v0, v1);
            *reinterpret_cast<float2*>(&C[(size_t)(row0 + 8) * N + col]) = make_float2(v2, v3);
        }
    }
}

// ---------------------------------------------------------------------------
// K2: per (b,h): kv[d][e] = sum_n k[n,d]*v[n,e];  ksum[d] = sum_n k[n,d]
// ---------------------------------------------------------------------------
__global__ __launch_bounds__(256) void kv_state_kernel()
{
    const int bh = blockIdx.x;
    const int b = bh >> 4, h = bh & 15;

    __shared__ float Ks[32][64];
    __shared__ float Vs[32][64];

    const int tid = threadIdx.x;
    const int tx = tid & 15, ty = tid >> 4;
    const int lr = tid >> 3;
    const int lc = (tid & 7) * 8;

    const float* base = g_qkv + (size_t)b * SEQ * QKV_COLS;
    const int k_col = DIM + h * HDIM;
    const int v_col = 2 * DIM + h * HDIM;

    float acc[4][4];
#pragma unroll
    for (int i = 0; i < 4; i++)
#pragma unroll
        for (int j = 0; j < 4; j++) acc[i][j] = 0.f;
    float ksum = 0.f;

    for (int n0 = 0; n0 < SEQ; n0 += 32) {
        const float* kp = base + (size_t)(n0 + lr) * QKV_COLS + k_col + lc;
        const float* vp = base + (size_t)(n0 + lr) * QKV_COLS + v_col + lc;
        *reinterpret_cast<float4*>(&Ks[lr][lc])     = *reinterpret_cast<const float4*>(kp);
        *reinterpret_cast<float4*>(&Ks[lr][lc + 4]) = *reinterpret_cast<const float4*>(kp + 4);
        *reinterpret_cast<float4*>(&Vs[lr][lc])     = *reinterpret_cast<const float4*>(vp);
        *reinterpret_cast<float4*>(&Vs[lr][lc + 4]) = *reinterpret_cast<const float4*>(vp + 4);
        __syncthreads();

#pragma unroll 8
        for (int kk = 0; kk < 32; kk++) {
            float rk[4], rv[4];
            *reinterpret_cast<float4*>(rk) = *reinterpret_cast<float4*>(&Ks[kk][ty * 4]);
            *reinterpret_cast<float4*>(rv) = *reinterpret_cast<float4*>(&Vs[kk][tx * 4]);
#pragma unroll
            for (int i = 0; i < 4; i++)
#pragma unroll
                for (int j = 0; j < 4; j++)
                    acc[i][j] = fmaf(rk[i], rv[j], acc[i][j]);
        }
        if (tid < 64) {
#pragma unroll
            for (int kk = 0; kk < 32; kk++) ksum += Ks[kk][tid];
        }
        __syncthreads();
    }

    float* kvout = g_kv + (size_t)bh * HDIM * HDIM;
#pragma unroll
    for (int i = 0; i < 4; i++) {
        float4 v = make_float4(acc[i][0], acc[i][1], acc[i][2], acc[i][3]);
        *reinterpret_cast<float4*>(&kvout[(ty * 4 + i) * HDIM + tx * 4]) = v;
    }
    if (tid < 64) g_ksum[bh * HDIM + tid] = ksum;
}

// ---------------------------------------------------------------------------
// K3: out = (q @ kv) * z ; z = 1/(q . ksum + 1e-6)
// ---------------------------------------------------------------------------
__global__ __launch_bounds__(256) void attn_out_kernel()
{
    const int bh = blockIdx.y;
    const int b = bh >> 4, h = bh & 15;
    const int n0 = blockIdx.x * 64;

    __shared__ float Qs[64][65];
    __shared__ float KVs[64 * 64];
    __shared__ float ksums[64];
    __shared__ float zsh[64];

    const int tid = threadIdx.x;

    const float* kvsrc = g_kv + (size_t)bh * HDIM * HDIM;
    for (int i = tid; i < (HDIM * HDIM) / 4; i += 256)
        reinterpret_cast<float4*>(KVs)[i] = reinterpret_cast<const float4*>(kvsrc)[i];
    if (tid < 64) ksums[tid] = g_ksum[bh * HDIM + tid];

    {
        const int qr = tid >> 2;
        const int qc = (tid & 3) * 16;
        const float* qbase = g_qkv + (size_t)(b * SEQ + n0 + qr) * QKV_COLS + h * HDIM + qc;
#pragma unroll
        for (int c = 0; c < 16; c += 4) {
            float4 v = *reinterpret_cast<const float4*>(qbase + c);
            Qs[qr][qc + c + 0] = v.x;
            Qs[qr][qc + c + 1] = v.y;
            Qs[qr][qc + c + 2] = v.z;
            Qs[qr][qc + c + 3] = v.w;
        }
    }
    __syncthreads();

    if (tid < 64) {
        float dot = 0.f;
#pragma unroll 8
        for (int d = 0; d < 64; d++) dot = fmaf(Qs[tid][d], ksums[d], dot);
        zsh[tid] = 1.f / (dot + 1e-6f);
    }
    __syncthreads();

    const int tx = tid & 15, ty = tid >> 4;
    const int r0 = ty * 4;
    const int e0 = tx * 4;

    float acc[4][4];
#pragma unroll
    for (int i = 0; i < 4; i++)
#pragma unroll
        for (int j = 0; j < 4; j++) acc[i][j] = 0.f;

#pragma unroll 4
    for (int d = 0; d < 64; d++) {
        float rb[4];
        *reinterpret_cast<float4*>(rb) = *reinterpret_cast<float4*>(&KVs[d * 64 + e0]);
        float ra0 = Qs[r0 + 0][d];
        float ra1 = Qs[r0 + 1][d];
        float ra2 = Qs[r0 + 2][d];
        float ra3 = Qs[r0 + 3][d];
#pragma unroll
        for (int j = 0; j < 4; j++) {
            acc[0][j] = fmaf(ra0, rb[j], acc[0][j]);
            acc[1][j] = fmaf(ra1, rb[j], acc[1][j]);
            acc[2][j] = fmaf(ra2, rb[j], acc[2][j]);
            acc[3][j] = fmaf(ra3, rb[j], acc[3][j]);
        }
    }

#pragma unroll
    for (int i = 0; i < 4; i++) {
        float z = zsh[r0 + i];
        float4 v = make_float4(acc[i][0] * z, acc[i][1] * z, acc[i][2] * z, acc[i][3] * z);
        size_t row = (size_t)(b * SEQ + n0 + r0 + i);
        *reinterpret_cast<float4*>(&g_attn[row * DIM + h * HDIM + e0]) = v;
    }
}

// ---------------------------------------------------------------------------
extern "C" void kernel_launch(void* const* d_in, const int* in_sizes, int n_in,
                              void* d_out, int out_size)
{
    const float* x      = (const float*)d_in[0];  // [4,4096,1024]
    const float* W_qkv  = (const float*)d_in[1];  // [1024,3072]
    const float* W_proj = (const float*)d_in[2];  // [1024,1024]
    const float* b_proj = (const float*)d_in[3];  // [1024]
    float* out = (float*)d_out;

    float *qkv_p, *attn_p;
    cudaGetSymbolAddress((void**)&qkv_p, g_qkv);
    cudaGetSymbolAddress((void**)&attn_p, g_attn);

    cudaFuncSetAttribute(gemm_mma<1>, cudaFuncAttributeMaxDynamicSharedMemorySize, SMEM_BYTES);
    cudaFuncSetAttribute(gemm_mma<2>, cudaFuncAttributeMaxDynamicSharedMemorySize, SMEM_BYTES);

    // K1: qkv = x @ W_qkv, elu+1 fused on q/k columns
    gemm_mma<1><<<dim3(QKV_COLS / 128, M_ROWS / 128), 256, SMEM_BYTES>>>(
        x, W_qkv, qkv_p, QKV_COLS, nullptr);

    // K2: kv state + ksum per (b,h)
    kv_state_kernel<<<BATCH * NHEAD, 256>>>();

    // K3: normalized readout
    attn_out_kernel<<<dim3(SEQ / 64, BATCH * NHEAD), 256>>>();

    // K4: out = attn @ W_proj + b_proj
    gemm_mma<2><<<dim3(DIM / 128, M_ROWS / 128), 256, SMEM_BYTES>>>(
        attn_p, W_proj, out, DIM, b_proj);
}

// round 4
// speedup vs baseline: 3.4072x; 1.3252x over previous
#include <cuda_runtime.h>
#include <math.h>
#include <stdint.h>

// ---------------------------------------------------------------------------
// Problem constants
// ---------------------------------------------------------------------------
#define BATCH 4
#define SEQ 4096
#define DIM 1024
#define NHEAD 16
#define HDIM 64
#define M_ROWS (BATCH * SEQ)      // 16384
#define QKV_COLS (3 * DIM)        // 3072
#define NCHUNK 16                 // K2 sequence split
#define CHUNK_ROWS (SEQ / NCHUNK) // 256

// Scratch (device globals; allocation-free contract)
__device__ float g_qkv[(size_t)M_ROWS * QKV_COLS];
__device__ float g_attn[(size_t)M_ROWS * DIM];
__device__ float g_xr[(size_t)M_ROWS * DIM];
__device__ float g_wqkvr[(size_t)DIM * QKV_COLS];
__device__ float g_wprojr[(size_t)DIM * DIM];
__device__ float g_kv[BATCH * NHEAD * HDIM * HDIM];
__device__ float g_ksum[BATCH * NHEAD * HDIM];
__device__ float g_kvp[NCHUNK * BATCH * NHEAD * HDIM * HDIM];
__device__ float g_ksump[NCHUNK * BATCH * NHEAD * HDIM];

// ---------------------------------------------------------------------------
// Smem geometry (pitches picked for conflict-free fragment LDS)
// ---------------------------------------------------------------------------
#define APITCH 36                       // floats per A row
#define BPITCH 136                      // floats per B row
#define A_ST_FLOATS (128 * APITCH)      // 4608
#define B_ST_FLOATS (32 * BPITCH)       // 4352
#define SMEM_FLOATS (2 * (A_ST_FLOATS + B_ST_FLOATS))
#define SMEM_BYTES (SMEM_FLOATS * 4)    // 71680

__device__ __forceinline__ uint32_t smem_u32(const void* p) {
    uint32_t a;
    asm("{ .reg .u64 t; cvta.to.shared.u64 t, %1; cvt.u32.u64 %0, t; }"
        : "=r"(a) : "l"(p));
    return a;
}
__device__ __forceinline__ void cp16(uint32_t dst, const void* src) {
    asm volatile("cp.async.cg.shared.global [%0], [%1], 16;" :: "r"(dst), "l"(src));
}
__device__ __forceinline__ float f2tf32(float f) {
    float r;
    asm("cvt.rna.tf32.f32 %0, %1;" : "=f"(r) : "f"(f));
    return r;
}
__device__ __forceinline__ void mma_m16n8k8(float* c, const uint32_t* a, const uint32_t* b) {
    asm volatile(
        "mma.sync.aligned.m16n8k8.row.col.f32.tf32.tf32.f32 "
        "{%0,%1,%2,%3}, {%4,%5,%6,%7}, {%8,%9}, {%0,%1,%2,%3};"
        : "+f"(c[0]), "+f"(c[1]), "+f"(c[2]), "+f"(c[3])
        : "r"(a[0]), "r"(a[1]), "r"(a[2]), "r"(a[3]), "r"(b[0]), "r"(b[1]));
}

// ---------------------------------------------------------------------------
// Tensor-core GEMM: C[M,N] = A[M,1024] @ B[1024,N], inputs pre-rounded tf32.
// CTA 128x128, 4 warps (warp tile 64x64), K-tile 32, cp.async double buffer.
// MODE 1: elu(v)+1 on global cols < 2048 ; MODE 2: v += bias[col]
// ---------------------------------------------------------------------------
template <int MODE>
__global__ __launch_bounds__(128, 2) void gemm_mma(
    const float* __restrict__ A, const float* __restrict__ B,
    float* __restrict__ C, int N, const float* __restrict__ bias)
{
    extern __shared__ float sm[];
    float* As = sm;                       // [2][128][APITCH]
    float* Bs = sm + 2 * A_ST_FLOATS;     // [2][32][BPITCH]

    const int tid = threadIdx.x;
    const int bm = blockIdx.y * 128;
    const int bn = blockIdx.x * 128;
    const int lane = tid & 31, wid = tid >> 5;
    const int g = lane >> 2, tg = lane & 3;
    const int mw = (wid >> 1) * 64;       // warp M offset
    const int nw = (wid & 1) * 64;        // warp N offset

    float acc[4][8][4];
#pragma unroll
    for (int mi = 0; mi < 4; mi++)
#pragma unroll
        for (int ni = 0; ni < 8; ni++)
#pragma unroll
            for (int j = 0; j < 4; j++) acc[mi][ni][j] = 0.f;

    const uint32_t sA = smem_u32(As);
    const uint32_t sB = smem_u32(Bs);

    // ---- tile loader (cp.async, 16B chunks; 128 threads -> 8 iters each) ----
    auto load_tile = [&](int kt, int s) {
#pragma unroll
        for (int i = 0; i < 8; i++) {               // A: 128 x 32 floats
            int c = tid + i * 128;
            int row = c >> 3;
            int off = (c & 7) * 4;
            const float* gp = A + (size_t)(bm + row) * DIM + kt * 32 + off;
            cp16(sA + (s * A_ST_FLOATS + row * APITCH + off) * 4, gp);
        }
#pragma unroll
        for (int i = 0; i < 8; i++) {               // B: 32 x 128 floats
            int c = tid + i * 128;
            int row = c >> 5;
            int col = (c & 31) * 4;
            const float* gp = B + (size_t)(kt * 32 + row) * N + bn + col;
            cp16(sB + (s * B_ST_FLOATS + row * BPITCH + col) * 4, gp);
        }
        asm volatile("cp.async.commit_group;" ::: "memory");
    };

    load_tile(0, 0);

    const int NT = DIM / 32;
    for (int kt = 0; kt < NT; ++kt) {
        const int s = kt & 1;
        if (kt + 1 < NT) {
            load_tile(kt + 1, (kt + 1) & 1);
            asm volatile("cp.async.wait_group 1;" ::: "memory");
        } else {
            asm volatile("cp.async.wait_group 0;" ::: "memory");
        }
        __syncthreads();

        const uint32_t* pa = reinterpret_cast<const uint32_t*>(As + s * A_ST_FLOATS);
        const uint32_t* pb = reinterpret_cast<const uint32_t*>(Bs + s * B_ST_FLOATS);

#pragma unroll
        for (int ks = 0; ks < 4; ks++) {
            const int k0 = ks * 8;
            uint32_t af[4][4];
#pragma unroll
            for (int mi = 0; mi < 4; mi++) {
                const int r0 = mw + mi * 16;
                af[mi][0] = pa[(r0 + g) * APITCH + k0 + tg];
                af[mi][1] = pa[(r0 + g + 8) * APITCH + k0 + tg];
                af[mi][2] = pa[(r0 + g) * APITCH + k0 + tg + 4];
                af[mi][3] = pa[(r0 + g + 8) * APITCH + k0 + tg + 4];
            }
            uint32_t bf[8][2];
#pragma unroll
            for (int ni = 0; ni < 8; ni++) {
                bf[ni][0] = pb[(k0 + tg) * BPITCH + nw + ni * 8 + g];
                bf[ni][1] = pb[(k0 + tg + 4) * BPITCH + nw + ni * 8 + g];
            }
#pragma unroll
            for (int mi = 0; mi < 4; mi++)
#pragma unroll
                for (int ni = 0; ni < 8; ni++)
                    mma_m16n8k8(acc[mi][ni], af[mi], bf[ni]);
        }
        __syncthreads();
    }

    // ---- epilogue ----
#pragma unroll
    for (int mi = 0; mi < 4; mi++) {
#pragma unroll
        for (int ni = 0; ni < 8; ni++) {
            const int row0 = bm + mw + mi * 16 + g;
            const int col = bn + nw + ni * 8 + 2 * tg;
            float v0 = acc[mi][ni][0], v1 = acc[mi][ni][1];
            float v2 = acc[mi][ni][2], v3 = acc[mi][ni][3];
            if (MODE == 1 && col < 2048) {          // elu(x)+1 on q,k columns
                v0 = (v0 > 0.f) ? (v0 + 1.f) : expf(v0);
                v1 = (v1 > 0.f) ? (v1 + 1.f) : expf(v1);
                v2 = (v2 > 0.f) ? (v2 + 1.f) : expf(v2);
                v3 = (v3 > 0.f) ? (v3 + 1.f) : expf(v3);
            }
            if (MODE == 2) {
                float b0 = __ldg(&bias[col]), b1 = __ldg(&bias[col + 1]);
                v0 += b0; v1 += b1; v2 += b0; v3 += b1;
            }
            *reinterpret_cast<float2*>(&C[(size_t)row0 * N + col]) = make_float2(v0, v1);
            *reinterpret_cast<float2*>(&C[(size_t)(row0 + 8) * N + col]) = make_float2(v2, v3);
        }
    }
}

// ---------------------------------------------------------------------------
// Streaming tf32 rounding pass
// ---------------------------------------------------------------------------
__global__ void round_tf32_kernel(const float4* __restrict__ in,
                                  float4* __restrict__ outp, int n4)
{
    int i = blockIdx.x * blockDim.x + threadIdx.x;
    int stride = gridDim.x * blockDim.x;
    for (; i < n4; i += stride) {
        float4 v = in[i];
        v.x = f2tf32(v.x); v.y = f2tf32(v.y); v.z = f2tf32(v.z); v.w = f2tf32(v.w);
        outp[i] = v;
    }
}

// ---------------------------------------------------------------------------
// K2a: partial kv/ksum per (chunk, b, h) over CHUNK_ROWS sequence positions
// ---------------------------------------------------------------------------
__global__ __launch_bounds__(256) void kv_partial_kernel()
{
    const int bh = blockIdx.x;              // 0..63
    const int chunk = blockIdx.y;           // 0..NCHUNK-1
    const int b = bh >> 4, h = bh & 15;

    __shared__ float Ks[32][64];
    __shared__ float Vs[32][64];

    const int tid = threadIdx.x;
    const int tx = tid & 15, ty = tid >> 4;
    const int lr = tid >> 3;
    const int lc = (tid & 7) * 8;

    const float* base = g_qkv + (size_t)b * SEQ * QKV_COLS;
    const int k_col = DIM + h * HDIM;
    const int v_col = 2 * DIM + h * HDIM;

    float acc[4][4];
#pragma unroll
    for (int i = 0; i < 4; i++)
#pragma unroll
        for (int j = 0; j < 4; j++) acc[i][j] = 0.f;
    float ksum = 0.f;

    const int nbeg = chunk * CHUNK_ROWS;
    for (int n0 = nbeg; n0 < nbeg + CHUNK_ROWS; n0 += 32) {
        const float* kp = base + (size_t)(n0 + lr) * QKV_COLS + k_col + lc;
        const float* vp = base + (size_t)(n0 + lr) * QKV_COLS + v_col + lc;
        *reinterpret_cast<float4*>(&Ks[lr][lc])     = *reinterpret_cast<const float4*>(kp);
        *reinterpret_cast<float4*>(&Ks[lr][lc + 4]) = *reinterpret_cast<const float4*>(kp + 4);
        *reinterpret_cast<float4*>(&Vs[lr][lc])     = *reinterpret_cast<const float4*>(vp);
        *reinterpret_cast<float4*>(&Vs[lr][lc + 4]) = *reinterpret_cast<const float4*>(vp + 4);
        __syncthreads();

#pragma unroll 8
        for (int kk = 0; kk < 32; kk++) {
            float rk[4], rv[4];
            *reinterpret_cast<float4*>(rk) = *reinterpret_cast<float4*>(&Ks[kk][ty * 4]);
            *reinterpret_cast<float4*>(rv) = *reinterpret_cast<float4*>(&Vs[kk][tx * 4]);
#pragma unroll
            for (int i = 0; i < 4; i++)
#pragma unroll
                for (int j = 0; j < 4; j++)
                    acc[i][j] = fmaf(rk[i], rv[j], acc[i][j]);
        }
        if (tid < 64) {
#pragma unroll
            for (int kk = 0; kk < 32; kk++) ksum += Ks[kk][tid];
        }
        __syncthreads();
    }

    float* kvout = g_kvp + ((size_t)chunk * 64 + bh) * HDIM * HDIM;
#pragma unroll
    for (int i = 0; i < 4; i++) {
        float4 v = make_float4(acc[i][0], acc[i][1], acc[i][2], acc[i][3]);
        *reinterpret_cast<float4*>(&kvout[(ty * 4 + i) * HDIM + tx * 4]) = v;
    }
    if (tid < 64) g_ksump[(chunk * 64 + bh) * HDIM + tid] = ksum;
}

// K2b: deterministic reduction over chunks
__global__ __launch_bounds__(256) void kv_reduce_kernel()
{
    const int bh = blockIdx.x;
    const int tid = threadIdx.x;
    for (int e = tid; e < HDIM * HDIM; e += 256) {
        float s = 0.f;
#pragma unroll
        for (int c = 0; c < NCHUNK; c++)
            s += g_kvp[((size_t)c * 64 + bh) * HDIM * HDIM + e];
        g_kv[(size_t)bh * HDIM * HDIM + e] = s;
    }
    if (tid < HDIM) {
        float s = 0.f;
#pragma unroll
        for (int c = 0; c < NCHUNK; c++)
            s += g_ksump[(c * 64 + bh) * HDIM + tid];
        g_ksum[bh * HDIM + tid] = s;
    }
}

// ---------------------------------------------------------------------------
// K3: out = (q @ kv) * z ; z = 1/(q . ksum + 1e-6); store tf32-rounded
// ---------------------------------------------------------------------------
__global__ __launch_bounds__(256) void attn_out_kernel()
{
    const int bh = blockIdx.y;
    const int b = bh >> 4, h = bh & 15;
    const int n0 = blockIdx.x * 64;

    __shared__ float Qs[64][65];
    __shared__ float KVs[64 * 64];
    __shared__ float ksums[64];
    __shared__ float zsh[64];

    const int tid = threadIdx.x;

    const float* kvsrc = g_kv + (size_t)bh * HDIM * HDIM;
    for (int i = tid; i < (HDIM * HDIM) / 4; i += 256)
        reinterpret_cast<float4*>(KVs)[i] = reinterpret_cast<const float4*>(kvsrc)[i];
    if (tid < 64) ksums[tid] = g_ksum[bh * HDIM + tid];

    {
        const int qr = tid >> 2;
        const int qc = (tid & 3) * 16;
        const float* qbase = g_qkv + (size_t)(b * SEQ + n0 + qr) * QKV_COLS + h * HDIM + qc;
#pragma unroll
        for (int c = 0; c < 16; c += 4) {
            float4 v = *reinterpret_cast<const float4*>(qbase + c);
            Qs[qr][qc + c + 0] = v.x;
            Qs[qr][qc + c + 1] = v.y;
            Qs[qr][qc + c + 2] = v.z;
            Qs[qr][qc + c + 3] = v.w;
        }
    }
    __syncthreads();

    if (tid < 64) {
        float dot = 0.f;
#pragma unroll 8
        for (int d = 0; d < 64; d++) dot = fmaf(Qs[tid][d], ksums[d], dot);
        zsh[tid] = 1.f / (dot + 1e-6f);
    }
    __syncthreads();

    const int tx = tid & 15, ty = tid >> 4;
    const int r0 = ty * 4;
    const int e0 = tx * 4;

    float acc[4][4];
#pragma unroll
    for (int i = 0; i < 4; i++)
#pragma unroll
        for (int j = 0; j < 4; j++) acc[i][j] = 0.f;

#pragma unroll 4
    for (int d = 0; d < 64; d++) {
        float rb[4];
        *reinterpret_cast<float4*>(rb) = *reinterpret_cast<float4*>(&KVs[d * 64 + e0]);
        float ra0 = Qs[r0 + 0][d];
        float ra1 = Qs[r0 + 1][d];
        float ra2 = Qs[r0 + 2][d];
        float ra3 = Qs[r0 + 3][d];
#pragma unroll
        for (int j = 0; j < 4; j++) {
            acc[0][j] = fmaf(ra0, rb[j], acc[0][j]);
            acc[1][j] = fmaf(ra1, rb[j], acc[1][j]);
            acc[2][j] = fmaf(ra2, rb[j], acc[2][j]);
            acc[3][j] = fmaf(ra3, rb[j], acc[3][j]);
        }
    }

#pragma unroll
    for (int i = 0; i < 4; i++) {
        float z = zsh[r0 + i];
        // tf32-rounded: this array is the A operand of the K4 tensor GEMM
        float4 v = make_float4(f2tf32(acc[i][0] * z), f2tf32(acc[i][1] * z),
                               f2tf32(acc[i][2] * z), f2tf32(acc[i][3] * z));
        size_t row = (size_t)(b * SEQ + n0 + r0 + i);
        *reinterpret_cast<float4*>(&g_attn[row * DIM + h * HDIM + e0]) = v;
    }
}

// ---------------------------------------------------------------------------
extern "C" void kernel_launch(void* const* d_in, const int* in_sizes, int n_in,
                              void* d_out, int out_size)
{
    const float* x      = (const float*)d_in[0];  // [4,4096,1024]
    const float* W_qkv  = (const float*)d_in[1];  // [1024,3072]
    const float* W_proj = (const float*)d_in[2];  // [1024,1024]
    const float* b_proj = (const float*)d_in[3];  // [1024]
    float* out = (float*)d_out;

    float *qkv_p, *attn_p, *xr_p, *wqkvr_p, *wprojr_p;
    cudaGetSymbolAddress((void**)&qkv_p, g_qkv);
    cudaGetSymbolAddress((void**)&attn_p, g_attn);
    cudaGetSymbolAddress((void**)&xr_p, g_xr);
    cudaGetSymbolAddress((void**)&wqkvr_p, g_wqkvr);
    cudaGetSymbolAddress((void**)&wprojr_p, g_wprojr);

    cudaFuncSetAttribute(gemm_mma<1>, cudaFuncAttributeMaxDynamicSharedMemorySize, SMEM_BYTES);
    cudaFuncSetAttribute(gemm_mma<2>, cudaFuncAttributeMaxDynamicSharedMemorySize, SMEM_BYTES);

    // tf32 pre-rounding passes (removes cvt from GEMM inner loops)
    round_tf32_kernel<<<2048, 256>>>((const float4*)x, (float4*)xr_p,
                                     (int)((size_t)M_ROWS * DIM / 4));
    round_tf32_kernel<<<1024, 256>>>((const float4*)W_qkv, (float4*)wqkvr_p,
                                     (int)((size_t)DIM * QKV_COLS / 4));
    round_tf32_kernel<<<512, 256>>>((const float4*)W_proj, (float4*)wprojr_p,
                                    (int)((size_t)DIM * DIM / 4));

    // K1: qkv = x @ W_qkv, elu+1 fused on q/k columns
    gemm_mma<1><<<dim3(QKV_COLS / 128, M_ROWS / 128), 128, SMEM_BYTES>>>(
        xr_p, wqkvr_p, qkv_p, QKV_COLS, nullptr);

    // K2: kv state + ksum (chunked + deterministic reduce)
    kv_partial_kernel<<<dim3(BATCH * NHEAD, NCHUNK), 256>>>();
    kv_reduce_kernel<<<BATCH * NHEAD, 256>>>();

    // K3: normalized readout (stores tf32-rounded)
    attn_out_kernel<<<dim3(SEQ / 64, BATCH * NHEAD), 256>>>();

    // K4: out = attn @ W_proj + b_proj
    gemm_mma<2><<<dim3(DIM / 128, M_ROWS / 128), 128, SMEM_BYTES>>>(
        attn_p, wprojr_p, out, DIM, b_proj);
}